// round 13
// baseline (speedup 1.0000x reference)
#include <cuda_runtime.h>
#include <cuda_bf16.h>
#include <cuda_fp16.h>
#include <math.h>

// Problem constants: B=4, L=5000, D=128, H=8, d=16, K=32
#define LQ    5000
#define MROWS 20000          // B*L  (divisible by 32)
#define DDIM  128
#define KSEL  32
#define WELEM (DDIM*DDIM)    // 16384
#define NTILES (MROWS/32)    // 625 tiles of 32 rows

// Scratch (allocation-free rule: __device__ globals)
__device__ float  g_q[MROWS * DDIM];
__device__ __half g_kh[MROWS * DDIM];
__device__ __half g_vh[MROWS * DDIM];
__device__ float  g_attn[MROWS * DDIM];
__device__ __nv_bfloat16 g_whi[4 * WELEM];
__device__ __nv_bfloat16 g_wlo[4 * WELEM];

// ---------------------------------------------------------------------------
__device__ __forceinline__ void bf16_split(float v, __nv_bfloat16& hi, __nv_bfloat16& lo)
{
    hi = __float2bfloat16(v);
    lo = __float2bfloat16(v - __bfloat162float(hi));
}

// W conversion: 4 x 16384 elements (tiny, ~2 us)
__global__ __launch_bounds__(256) void convert_w(const float* __restrict__ wq,
                                                 const float* __restrict__ wk,
                                                 const float* __restrict__ wv,
                                                 const float* __restrict__ wo)
{
    int i = blockIdx.x * blockDim.x + threadIdx.x;
    if (i >= 4 * WELEM) return;
    const float* src[4] = { wq, wk, wv, wo };
    float v = src[i >> 14][i & (WELEM - 1)];
    __nv_bfloat16 hi, lo;
    bf16_split(v, hi, lo);
    g_whi[i] = hi;
    g_wlo[i] = lo;
}

// ---------------------------------------------------------------------------
// Persistent-W 3xBF16 tensor GEMM (R8 tiling) with cp.async W-prologue:
// the 64KB W (hi+lo) smem fill is fire-and-forget (no LDG->STS register
// dependency chain), overlapped with the first A-tile register stage.
// ---------------------------------------------------------------------------
#define MMA_BF16(d, a, b)                                                   \
    asm volatile(                                                           \
        "mma.sync.aligned.m16n8k16.row.col.f32.bf16.bf16.f32 "              \
        "{%0,%1,%2,%3}, {%4,%5,%6,%7}, {%8,%9}, {%0,%1,%2,%3};"             \
        : "+f"(d[0]), "+f"(d[1]), "+f"(d[2]), "+f"(d[3])                    \
        : "r"(a[0]), "r"(a[1]), "r"(a[2]), "r"(a[3]), "r"(b[0]), "r"(b[1]))

__device__ __forceinline__ void ldsm4(unsigned* r, unsigned addr)
{
    asm volatile("ldmatrix.sync.aligned.m8n8.x4.shared.b16 {%0,%1,%2,%3}, [%4];"
                 : "=r"(r[0]), "=r"(r[1]), "=r"(r[2]), "=r"(r[3]) : "r"(addr));
}

#define CP_ASYNC16(dst, src)                                                \
    asm volatile("cp.async.cg.shared.global [%0], [%1], 16;"                \
                 :: "r"(dst), "l"(src))

#define SROWW   136                        // row stride in bf16 elems (272 B)
#define WPLANE  (128 * SROWW)              // 17408 elems
#define ATILE   (32 * SROWW)               // 4352 elems per A plane
#define OFF_WL  WPLANE
#define OFF_A   (2 * WPLANE)               // A buffers start (hi,lo per buf)
#define ABUF    (2 * ATILE)                // one A buffer (hi+lo)
#define GSMEM_ELEM (2 * WPLANE + 2 * ABUF) // 52224 elems
#define GSMEM_BYTES (GSMEM_ELEM * 2)       // 104448 B

__global__ __launch_bounds__(256, 2) void gemm_bf16(const float* __restrict__ A,
                                                    const __nv_bfloat16* __restrict__ WhiB,
                                                    const __nv_bfloat16* __restrict__ WloB,
                                                    const float* __restrict__ bias,
                                                    float* __restrict__ Cf,
                                                    __half* __restrict__ Ck,
                                                    __half* __restrict__ Cv,
                                                    int wsel)
{
    extern __shared__ __nv_bfloat16 smem[];

    const int y    = blockIdx.y;
    const int widx = wsel + y;
    const __nv_bfloat16* Wh = WhiB + widx * WELEM;
    const __nv_bfloat16* Wl = WloB + widx * WELEM;

    const int tid  = threadIdx.x;
    const int w    = tid >> 5;
    const int lane = tid & 31;
    const int wm   = (w >> 2) * 16;     // 2 warps in m
    const int wn   = (w & 3) * 32;      // 4 warps in n
    const int fr   = lane >> 2;
    const int fc   = (lane & 3) * 2;

    const unsigned sbase = (unsigned)__cvta_generic_to_shared(&smem[0]);

    // ---- W prologue via cp.async (fire-and-forget, once) ----
    #pragma unroll
    for (int it = 0; it < 8; it++) {
        int i   = tid + it * 256;            // 0..2047 (uint4 granules)
        int row = i >> 4;
        int seg = i & 15;
        CP_ASYNC16(sbase + (unsigned)((row * SROWW + seg * 8) * 2),
                   &Wh[row * DDIM + seg * 8]);
        CP_ASYNC16(sbase + (unsigned)((OFF_WL + row * SROWW + seg * 8) * 2),
                   &Wl[row * DDIM + seg * 8]);
    }
    asm volatile("cp.async.commit_group;" ::: "memory");

    const unsigned laneA = (unsigned)((wm + (lane & 15)) * (SROWW * 2)
                                      + ((lane >> 4) & 1) * 16);
    const unsigned laneB = (unsigned)((wn + ((lane >> 4) & 1) * 8 + (lane & 7)) * (SROWW * 2)
                                      + ((lane >> 3) & 1) * 16);
    const unsigned aoff[2] = { (unsigned)(OFF_A * 2), (unsigned)((OFF_A + ABUF) * 2) };

    // A staging: thread owns row ar (8 thr/row), 16 floats at seg as*16
    const int ar = tid >> 3;            // 0..31
    const int as = tid & 7;

    float4 aR[4];
    auto stage = [&](int mt) {
        const float4* s = (const float4*)&A[(size_t)(mt * 32 + ar) * DDIM + as * 16];
        aR[0] = s[0]; aR[1] = s[1]; aR[2] = s[2]; aR[3] = s[3];
    };
    auto commit = [&](int b) {
        __nv_bfloat16* ah = &smem[OFF_A + b * ABUF];
        __nv_bfloat16* al = ah + ATILE;
        union { __nv_bfloat16 h[16]; uint4 u[2]; } H, L;
        const float* af = (const float*)aR;
        #pragma unroll
        for (int i = 0; i < 16; i++) bf16_split(af[i], H.h[i], L.h[i]);
        uint4* dh = (uint4*)&ah[ar * SROWW + as * 16];
        uint4* dl = (uint4*)&al[ar * SROWW + as * 16];
        dh[0] = H.u[0]; dh[1] = H.u[1];
        dl[0] = L.u[0]; dl[1] = L.u[1];
    };

    int mt = blockIdx.x;
    int buf = 0;
    if (mt < NTILES) { stage(mt); commit(0); }   // overlaps W cp.async flight
    asm volatile("cp.async.wait_group 0;" ::: "memory");
    __syncthreads();                     // W + first A commit visible

    while (mt < NTILES) {
        const int nxt = mt + gridDim.x;
        if (nxt < NTILES) stage(nxt);

        float acc[4][4] = {};
        const unsigned ab = sbase + aoff[buf];

        #pragma unroll
        for (int ks = 0; ks < 8; ks++) {
            unsigned ah[4], al[4];
            ldsm4(ah, ab + laneA + (unsigned)(ks * 32));
            ldsm4(al, ab + (unsigned)(ATILE * 2) + laneA + (unsigned)(ks * 32));
            #pragma unroll
            for (int ntp = 0; ntp < 2; ntp++) {
                unsigned bh[4], bl[4];
                const unsigned bo = laneB + (unsigned)(ntp * 16 * SROWW * 2 + ks * 32);
                ldsm4(bh, sbase + bo);
                ldsm4(bl, sbase + (unsigned)(OFF_WL * 2) + bo);
                MMA_BF16(acc[ntp * 2],     ah, (bh + 0));
                MMA_BF16(acc[ntp * 2],     ah, (bl + 0));
                MMA_BF16(acc[ntp * 2],     al, (bh + 0));
                MMA_BF16(acc[ntp * 2 + 1], ah, (bh + 2));
                MMA_BF16(acc[ntp * 2 + 1], ah, (bl + 2));
                MMA_BF16(acc[ntp * 2 + 1], al, (bh + 2));
            }
        }

        const int mrow = mt * 32 + wm + fr;
        if (y == 0) {
            #pragma unroll
            for (int nt = 0; nt < 4; nt++) {
                const int n = wn + nt * 8 + fc;
                float2 bb = make_float2(0.f, 0.f);
                if (bias) bb = *(const float2*)&bias[n];
                *(float2*)&Cf[(size_t)mrow * DDIM + n] =
                    make_float2(acc[nt][0] + bb.x, acc[nt][1] + bb.y);
                *(float2*)&Cf[(size_t)(mrow + 8) * DDIM + n] =
                    make_float2(acc[nt][2] + bb.x, acc[nt][3] + bb.y);
            }
        } else {
            __half* H = (y == 1) ? Ck : Cv;
            #pragma unroll
            for (int nt = 0; nt < 4; nt++) {
                const int n = wn + nt * 8 + fc;
                *(__half2*)&H[(size_t)mrow * DDIM + n] =
                    __floats2half2_rn(acc[nt][0], acc[nt][1]);
                *(__half2*)&H[(size_t)(mrow + 8) * DDIM + n] =
                    __floats2half2_rn(acc[nt][2], acc[nt][3]);
            }
        }

        if (nxt < NTILES) commit(buf ^ 1);
        __syncthreads();
        buf ^= 1;
        mt = nxt;
    }
}

// ---------------------------------------------------------------------------
// Attention v4: 128 thr / 1 query. Score phase loads TWO k-rows per warp
// per iteration (16B/lane) with lane j holding q[8j..8j+8): one shfl per
// iteration finishes each 16-dim head dot (score shfl 16 -> 4 per warp).
// V prefetch before softmax; no-max softmax; fp16 K/V, fp32 math.
// Warp w owns keys {8p + 2w + b : p in 0..3, b in 0..1}.
// ---------------------------------------------------------------------------
__global__ __launch_bounds__(128) void attn_kernel(const int* __restrict__ kidx)
{
    __shared__ int   sIdx[KSEL];
    __shared__ float sS[8][36];      // pad 36 -> conflict-free score stores
    __shared__ float sAcc[4][DDIM];

    const int bl   = blockIdx.x;
    const int l    = bl % LQ;
    const int base = bl - l;
    const int t    = threadIdx.x;
    const int w    = t >> 5;
    const int lane = t & 31;
    const int h    = lane >> 2;      // V-phase head (lane owns channels 4l..4l+3)
    const int b    = lane >> 4;      // score-phase row half (0/1)
    const int j    = lane & 15;      // score-phase column chunk (8 channels)

    if (t < KSEL) sIdx[t] = kidx[l * KSEL + t];

    // q chunk for score phase: lane j holds q[8j .. 8j+8)
    const float4 qa = *(const float4*)&g_q[(size_t)bl * DDIM + j * 8];
    const float4 qb = *(const float4*)&g_q[(size_t)bl * DDIM + j * 8 + 4];
    __syncthreads();

    // ---- score pass: iteration p -> keys 8p+2w (lanes 0-15), 8p+2w+1 (16-31)
    #pragma unroll
    for (int p = 0; p < 4; p++) {
        const int key = p * 8 + 2 * w + b;
        const int row = base + sIdx[key];
        const uint4 kv = *(const uint4*)&g_kh[(size_t)row * DDIM + j * 8];
        const float2 f0 = __half22float2(*(const __half2*)&kv.x);
        const float2 f1 = __half22float2(*(const __half2*)&kv.y);
        const float2 f2 = __half22float2(*(const __half2*)&kv.z);
        const float2 f3 = __half22float2(*(const __half2*)&kv.w);
        float s = f0.x * qa.x + f0.y * qa.y + f1.x * qa.z + f1.y * qa.w
                + f2.x * qb.x + f2.y * qb.y + f3.x * qb.z + f3.y * qb.w;
        s += __shfl_xor_sync(0xffffffffu, s, 1);   // join the two 8-ch halves
        if ((j & 1) == 0) sS[j >> 1][key] = s * 0.25f;
    }

    // ---- V prefetch for this warp's keys (independent of softmax) ----
    uint2 vv[8];
    #pragma unroll
    for (int i = 0; i < 8; i++) {
        const int key = (i >> 1) * 8 + 2 * w + (i & 1);
        vv[i] = *(const uint2*)&g_vh[(size_t)(base + sIdx[key]) * DDIM + lane * 4];
    }
    __syncthreads();

    // ---- softmax (no max subtraction): warp w -> heads 2w, 2w+1 ----
    #pragma unroll
    for (int jj = 0; jj < 2; jj++) {
        const int hh = w * 2 + jj;
        const float e = __expf(sS[hh][lane]);
        float sum = e;
        #pragma unroll
        for (int ofs = 16; ofs; ofs >>= 1)
            sum += __shfl_xor_sync(0xffffffffu, sum, ofs);
        sS[hh][lane] = e * __frcp_rn(sum);
    }
    __syncthreads();

    // ---- weighted V sum from registers ----
    float4 acc = make_float4(0.f, 0.f, 0.f, 0.f);
    #pragma unroll
    for (int i = 0; i < 8; i++) {
        const float2 f0 = __half22float2(*(const __half2*)&vv[i].x);
        const float2 f1 = __half22float2(*(const __half2*)&vv[i].y);
        const float a = sS[h][(i >> 1) * 8 + 2 * w + (i & 1)];
        acc.x += a * f0.x;
        acc.y += a * f0.y;
        acc.z += a * f1.x;
        acc.w += a * f1.y;
    }
    *(float4*)&sAcc[w][lane * 4] = acc;
    __syncthreads();

    g_attn[(size_t)bl * DDIM + t] = sAcc[0][t] + sAcc[1][t] + sAcc[2][t] + sAcc[3][t];
}

// ---------------------------------------------------------------------------
extern "C" void kernel_launch(void* const* d_in, const int* in_sizes, int n_in,
                              void* d_out, int out_size)
{
    const float* x    = (const float*)d_in[0];
    const int*   kidx = (const int*)d_in[1];
    const float* Wq   = (const float*)d_in[2];
    const float* Wk   = (const float*)d_in[3];
    const float* Wv   = (const float*)d_in[4];
    const float* Wo   = (const float*)d_in[5];
    const float* bo   = (const float*)d_in[6];
    float* out = (float*)d_out;

    float *q, *attn;
    __half *kh, *vh;
    __nv_bfloat16 *whi, *wlo;
    cudaGetSymbolAddress((void**)&q,    g_q);
    cudaGetSymbolAddress((void**)&kh,   g_kh);
    cudaGetSymbolAddress((void**)&vh,   g_vh);
    cudaGetSymbolAddress((void**)&attn, g_attn);
    cudaGetSymbolAddress((void**)&whi,  g_whi);
    cudaGetSymbolAddress((void**)&wlo,  g_wlo);

    // Raise dynamic smem cap (idempotent; not a stream op; every call).
    cudaFuncSetAttribute(gemm_bf16,
                         cudaFuncAttributeMaxDynamicSharedMemorySize,
                         GSMEM_BYTES);

    convert_w<<<(4 * WELEM + 255) / 256, 256>>>(Wq, Wk, Wv, Wo);

    // QKV: 96 x 3 persistent blocks (~2/SM), ~6.5 tiles each.
    gemm_bf16<<<dim3(96, 3), 256, GSMEM_BYTES>>>(x, whi, wlo, nullptr,
                                                 q, kh, vh, 0);

    attn_kernel<<<MROWS, 128>>>(kidx);

    // Wo: 296 persistent blocks (2/SM), ~2.1 tiles each, bias, fp32 out.
    gemm_bf16<<<dim3(296, 1), 256, GSMEM_BYTES>>>(attn, whi, wlo, bo,
                                                  out, nullptr, nullptr, 3);
}

// round 14
// speedup vs baseline: 1.2075x; 1.2075x over previous
#include <cuda_runtime.h>
#include <cuda_bf16.h>
#include <cuda_fp16.h>
#include <math.h>

// Problem constants: B=4, L=5000, D=128, H=8, d=16, K=32
#define LQ    5000
#define MROWS 20000          // B*L  (divisible by 32)
#define DDIM  128
#define KSEL  32
#define WELEM (DDIM*DDIM)    // 16384
#define NTILES (MROWS/32)    // 625 tiles of 32 rows

// Scratch (allocation-free rule: __device__ globals)
__device__ float  g_q[MROWS * DDIM];
__device__ __half g_kh[MROWS * DDIM];
__device__ __half g_vh[MROWS * DDIM];
__device__ float  g_attn[MROWS * DDIM];
__device__ __nv_bfloat16 g_whi[4 * WELEM];
__device__ __nv_bfloat16 g_wlo[4 * WELEM];

// ---------------------------------------------------------------------------
__device__ __forceinline__ void bf16_split(float v, __nv_bfloat16& hi, __nv_bfloat16& lo)
{
    hi = __float2bfloat16(v);
    lo = __float2bfloat16(v - __bfloat162float(hi));
}

// W conversion: 4 x 16384 elements (tiny, ~2 us)
__global__ __launch_bounds__(256) void convert_w(const float* __restrict__ wq,
                                                 const float* __restrict__ wk,
                                                 const float* __restrict__ wv,
                                                 const float* __restrict__ wo)
{
    int i = blockIdx.x * blockDim.x + threadIdx.x;
    if (i >= 4 * WELEM) return;
    const float* src[4] = { wq, wk, wv, wo };
    float v = src[i >> 14][i & (WELEM - 1)];
    __nv_bfloat16 hi, lo;
    bf16_split(v, hi, lo);
    g_whi[i] = hi;
    g_wlo[i] = lo;
}

// ---------------------------------------------------------------------------
// Persistent-W 3xBF16 tensor GEMM (R12 configuration — best measured):
// C[m][n] = sum_k A[m][k]*W[n][k] (+bias). W (hi+lo bf16) resident in smem;
// block grid-strides over 32-row A tiles, A double-buffered register-staged
// and split in-kernel. 256 thr / 8 warps, warp grid 2m x 4n (tile m16xn32).
// Row stride 136 elem (272 B): ldmatrix 8-row phases conflict-free.
// ---------------------------------------------------------------------------
#define MMA_BF16(d, a, b)                                                   \
    asm volatile(                                                           \
        "mma.sync.aligned.m16n8k16.row.col.f32.bf16.bf16.f32 "              \
        "{%0,%1,%2,%3}, {%4,%5,%6,%7}, {%8,%9}, {%0,%1,%2,%3};"             \
        : "+f"(d[0]), "+f"(d[1]), "+f"(d[2]), "+f"(d[3])                    \
        : "r"(a[0]), "r"(a[1]), "r"(a[2]), "r"(a[3]), "r"(b[0]), "r"(b[1]))

__device__ __forceinline__ void ldsm4(unsigned* r, unsigned addr)
{
    asm volatile("ldmatrix.sync.aligned.m8n8.x4.shared.b16 {%0,%1,%2,%3}, [%4];"
                 : "=r"(r[0]), "=r"(r[1]), "=r"(r[2]), "=r"(r[3]) : "r"(addr));
}

#define SROWW   136                        // row stride in bf16 elems (272 B)
#define WPLANE  (128 * SROWW)              // 17408 elems
#define ATILE   (32 * SROWW)               // 4352 elems per A plane
#define OFF_WL  WPLANE
#define OFF_A   (2 * WPLANE)               // A buffers start (hi,lo per buf)
#define ABUF    (2 * ATILE)                // one A buffer (hi+lo)
#define GSMEM_ELEM (2 * WPLANE + 2 * ABUF) // 52224 elems
#define GSMEM_BYTES (GSMEM_ELEM * 2)       // 104448 B

__global__ __launch_bounds__(256, 2) void gemm_bf16(const float* __restrict__ A,
                                                    const __nv_bfloat16* __restrict__ WhiB,
                                                    const __nv_bfloat16* __restrict__ WloB,
                                                    const float* __restrict__ bias,
                                                    float* __restrict__ Cf,
                                                    __half* __restrict__ Ck,
                                                    __half* __restrict__ Cv,
                                                    int wsel)
{
    extern __shared__ __nv_bfloat16 smem[];

    const int y    = blockIdx.y;
    const int widx = wsel + y;
    const __nv_bfloat16* Wh = WhiB + widx * WELEM;
    const __nv_bfloat16* Wl = WloB + widx * WELEM;

    const int tid  = threadIdx.x;
    const int w    = tid >> 5;
    const int lane = tid & 31;
    const int wm   = (w >> 2) * 16;     // 2 warps in m
    const int wn   = (w & 3) * 32;      // 4 warps in n
    const int fr   = lane >> 2;
    const int fc   = (lane & 3) * 2;

    // ---- load W (hi+lo bf16) into smem, once ----
    #pragma unroll
    for (int it = 0; it < 8; it++) {
        int i   = tid + it * 256;            // 0..2047 (uint4 granules)
        int row = i >> 4;
        int seg = i & 15;
        *(uint4*)&smem[row * SROWW + seg * 8] =
            *(const uint4*)&Wh[row * DDIM + seg * 8];
        *(uint4*)&smem[OFF_WL + row * SROWW + seg * 8] =
            *(const uint4*)&Wl[row * DDIM + seg * 8];
    }

    const unsigned sbase = (unsigned)__cvta_generic_to_shared(&smem[0]);
    const unsigned laneA = (unsigned)((wm + (lane & 15)) * (SROWW * 2)
                                      + ((lane >> 4) & 1) * 16);
    const unsigned laneB = (unsigned)((wn + ((lane >> 4) & 1) * 8 + (lane & 7)) * (SROWW * 2)
                                      + ((lane >> 3) & 1) * 16);
    const unsigned aoff[2] = { (unsigned)(OFF_A * 2), (unsigned)((OFF_A + ABUF) * 2) };

    // A staging: thread owns row ar (8 thr/row), 16 floats at seg as*16
    const int ar = tid >> 3;            // 0..31
    const int as = tid & 7;

    float4 aR[4];
    auto stage = [&](int mt) {
        const float4* s = (const float4*)&A[(size_t)(mt * 32 + ar) * DDIM + as * 16];
        aR[0] = s[0]; aR[1] = s[1]; aR[2] = s[2]; aR[3] = s[3];
    };
    auto commit = [&](int b) {
        __nv_bfloat16* ah = &smem[OFF_A + b * ABUF];
        __nv_bfloat16* al = ah + ATILE;
        union { __nv_bfloat16 h[16]; uint4 u[2]; } H, L;
        const float* af = (const float*)aR;
        #pragma unroll
        for (int i = 0; i < 16; i++) bf16_split(af[i], H.h[i], L.h[i]);
        uint4* dh = (uint4*)&ah[ar * SROWW + as * 16];
        uint4* dl = (uint4*)&al[ar * SROWW + as * 16];
        dh[0] = H.u[0]; dh[1] = H.u[1];
        dl[0] = L.u[0]; dl[1] = L.u[1];
    };

    int mt = blockIdx.x;
    int buf = 0;
    if (mt < NTILES) { stage(mt); commit(0); }
    __syncthreads();                     // covers W load + first A commit

    while (mt < NTILES) {
        const int nxt = mt + gridDim.x;
        if (nxt < NTILES) stage(nxt);

        float acc[4][4] = {};
        const unsigned ab = sbase + aoff[buf];

        #pragma unroll
        for (int ks = 0; ks < 8; ks++) {
            unsigned ah[4], al[4];
            ldsm4(ah, ab + laneA + (unsigned)(ks * 32));
            ldsm4(al, ab + (unsigned)(ATILE * 2) + laneA + (unsigned)(ks * 32));
            #pragma unroll
            for (int ntp = 0; ntp < 2; ntp++) {
                unsigned bh[4], bl[4];
                const unsigned bo = laneB + (unsigned)(ntp * 16 * SROWW * 2 + ks * 32);
                ldsm4(bh, sbase + bo);
                ldsm4(bl, sbase + (unsigned)(OFF_WL * 2) + bo);
                MMA_BF16(acc[ntp * 2],     ah, (bh + 0));
                MMA_BF16(acc[ntp * 2],     ah, (bl + 0));
                MMA_BF16(acc[ntp * 2],     al, (bh + 0));
                MMA_BF16(acc[ntp * 2 + 1], ah, (bh + 2));
                MMA_BF16(acc[ntp * 2 + 1], ah, (bl + 2));
                MMA_BF16(acc[ntp * 2 + 1], al, (bh + 2));
            }
        }

        const int mrow = mt * 32 + wm + fr;
        if (y == 0) {
            #pragma unroll
            for (int nt = 0; nt < 4; nt++) {
                const int n = wn + nt * 8 + fc;
                float2 bb = make_float2(0.f, 0.f);
                if (bias) bb = *(const float2*)&bias[n];
                *(float2*)&Cf[(size_t)mrow * DDIM + n] =
                    make_float2(acc[nt][0] + bb.x, acc[nt][1] + bb.y);
                *(float2*)&Cf[(size_t)(mrow + 8) * DDIM + n] =
                    make_float2(acc[nt][2] + bb.x, acc[nt][3] + bb.y);
            }
        } else {
            __half* H = (y == 1) ? Ck : Cv;
            #pragma unroll
            for (int nt = 0; nt < 4; nt++) {
                const int n = wn + nt * 8 + fc;
                *(__half2*)&H[(size_t)mrow * DDIM + n] =
                    __floats2half2_rn(acc[nt][0], acc[nt][1]);
                *(__half2*)&H[(size_t)(mrow + 8) * DDIM + n] =
                    __floats2half2_rn(acc[nt][2], acc[nt][3]);
            }
        }

        if (nxt < NTILES) commit(buf ^ 1);
        __syncthreads();
        buf ^= 1;
        mt = nxt;
    }
}

// ---------------------------------------------------------------------------
// Attention v5: ONE WARP PER QUERY. Zero smem, zero block barriers.
// 8 queries per 256-thr block; warps fully independent.
// Lane layout: j = lane&15 owns channels [8j, 8j+8); b = lane>>4 = key half.
// Score iter i: key 2i+b; LDG.128 covers 2 k-rows (16 B/lane); shfl_xor(1)
// joins the two 8-ch halves of each head -> BOTH paired lanes hold the head
// score (so V-phase weights need no broadcast). Scores live in regs s[16].
// Softmax: per-lane exp over 16 regs + one shfl_xor(16) to join key halves
// (no max subtraction: scores ~N(0,1)). V: 16x(LDG.128 + 8 FMA) in regs;
// final 8x shfl_xor(16), lanes 0-15 store 32 B each (coalesced 512 B).
// ---------------------------------------------------------------------------
__global__ __launch_bounds__(256) void attn_kernel(const int* __restrict__ kidx)
{
    const int W    = threadIdx.x >> 5;
    const int lane = threadIdx.x & 31;
    const int bl   = blockIdx.x * 8 + W;       // query row (b*L + l)
    const int l    = bl % LQ;
    const int base = bl - l;
    const int b    = lane >> 4;                // key half (0/1)
    const int j    = lane & 15;                // channel chunk

    // lane i holds key i's index
    const int myIdx = kidx[l * KSEL + lane];

    // q chunk: channels [8j, 8j+8)
    const float4 qa = *(const float4*)&g_q[(size_t)bl * DDIM + j * 8];
    const float4 qb = *(const float4*)&g_q[(size_t)bl * DDIM + j * 8 + 4];

    // ---- score phase ----
    float s[16];
    #pragma unroll
    for (int i = 0; i < 16; i++) {
        const int key = 2 * i + b;
        const int row = base + __shfl_sync(0xffffffffu, myIdx, key);
        const uint4 kv = *(const uint4*)&g_kh[(size_t)row * DDIM + j * 8];
        const float2 f0 = __half22float2(*(const __half2*)&kv.x);
        const float2 f1 = __half22float2(*(const __half2*)&kv.y);
        const float2 f2 = __half22float2(*(const __half2*)&kv.z);
        const float2 f3 = __half22float2(*(const __half2*)&kv.w);
        float p = f0.x * qa.x + f0.y * qa.y + f1.x * qa.z + f1.y * qa.w
                + f2.x * qb.x + f2.y * qb.y + f3.x * qb.z + f3.y * qb.w;
        p += __shfl_xor_sync(0xffffffffu, p, 1);   // join 8-ch halves of head j>>1
        s[i] = p * 0.25f;                          // scale = 1/sqrt(16)
    }

    // ---- softmax over this head's 32 keys (no max subtraction) ----
    float sum = 0.f;
    #pragma unroll
    for (int i = 0; i < 16; i++) {
        s[i] = __expf(s[i]);
        sum += s[i];
    }
    sum += __shfl_xor_sync(0xffffffffu, sum, 16);  // join key halves
    const float inv = __frcp_rn(sum);

    // ---- V phase: lane accumulates channels [8j, 8j+8) over its 16 keys ----
    float acc[8] = {};
    #pragma unroll
    for (int i = 0; i < 16; i++) {
        const int key = 2 * i + b;
        const int row = base + __shfl_sync(0xffffffffu, myIdx, key);
        const uint4 vv = *(const uint4*)&g_vh[(size_t)row * DDIM + j * 8];
        const float2 f0 = __half22float2(*(const __half2*)&vv.x);
        const float2 f1 = __half22float2(*(const __half2*)&vv.y);
        const float2 f2 = __half22float2(*(const __half2*)&vv.z);
        const float2 f3 = __half22float2(*(const __half2*)&vv.w);
        const float a = s[i] * inv;
        acc[0] += a * f0.x; acc[1] += a * f0.y;
        acc[2] += a * f1.x; acc[3] += a * f1.y;
        acc[4] += a * f2.x; acc[5] += a * f2.y;
        acc[6] += a * f3.x; acc[7] += a * f3.y;
    }

    // ---- join key halves, store ----
    #pragma unroll
    for (int c = 0; c < 8; c++)
        acc[c] += __shfl_xor_sync(0xffffffffu, acc[c], 16);

    if (b == 0) {
        *(float4*)&g_attn[(size_t)bl * DDIM + j * 8] =
            make_float4(acc[0], acc[1], acc[2], acc[3]);
        *(float4*)&g_attn[(size_t)bl * DDIM + j * 8 + 4] =
            make_float4(acc[4], acc[5], acc[6], acc[7]);
    }
}

// ---------------------------------------------------------------------------
extern "C" void kernel_launch(void* const* d_in, const int* in_sizes, int n_in,
                              void* d_out, int out_size)
{
    const float* x    = (const float*)d_in[0];
    const int*   kidx = (const int*)d_in[1];
    const float* Wq   = (const float*)d_in[2];
    const float* Wk   = (const float*)d_in[3];
    const float* Wv   = (const float*)d_in[4];
    const float* Wo   = (const float*)d_in[5];
    const float* bo   = (const float*)d_in[6];
    float* out = (float*)d_out;

    float *q, *attn;
    __half *kh, *vh;
    __nv_bfloat16 *whi, *wlo;
    cudaGetSymbolAddress((void**)&q,    g_q);
    cudaGetSymbolAddress((void**)&kh,   g_kh);
    cudaGetSymbolAddress((void**)&vh,   g_vh);
    cudaGetSymbolAddress((void**)&attn, g_attn);
    cudaGetSymbolAddress((void**)&whi,  g_whi);
    cudaGetSymbolAddress((void**)&wlo,  g_wlo);

    // Raise dynamic smem cap (idempotent; not a stream op; every call).
    cudaFuncSetAttribute(gemm_bf16,
                         cudaFuncAttributeMaxDynamicSharedMemorySize,
                         GSMEM_BYTES);

    convert_w<<<(4 * WELEM + 255) / 256, 256>>>(Wq, Wk, Wv, Wo);

    // QKV: 96 x 3 persistent blocks (~2/SM), ~6.5 tiles each.
    gemm_bf16<<<dim3(96, 3), 256, GSMEM_BYTES>>>(x, whi, wlo, nullptr,
                                                 q, kh, vh, 0);

    // Attention: 1 warp per query, 8 queries/block, 2500 blocks.
    attn_kernel<<<MROWS / 8, 256>>>(kidx);

    // Wo: 296 persistent blocks (2/SM), ~2.1 tiles each, bias, fp32 out.
    gemm_bf16<<<dim3(296, 1), 256, GSMEM_BYTES>>>(attn, whi, wlo, bo,
                                                  out, nullptr, nullptr, 3);
}

// round 15
// speedup vs baseline: 1.3146x; 1.0887x over previous
#include <cuda_runtime.h>
#include <cuda_bf16.h>
#include <cuda_fp16.h>
#include <math.h>

// Problem constants: B=4, L=5000, D=128, H=8, d=16, K=32
#define LQ    5000
#define MROWS 20000          // B*L  (divisible by 32)
#define DDIM  128
#define KSEL  32
#define WELEM (DDIM*DDIM)    // 16384
#define NTILES (MROWS/32)    // 625 tiles of 32 rows

// Scratch (allocation-free rule: __device__ globals)
__device__ float  g_q[MROWS * DDIM];
__device__ __half g_kh[MROWS * DDIM];
__device__ __half g_vh[MROWS * DDIM];
__device__ float  g_attn[MROWS * DDIM];
__device__ __half g_whi[4 * WELEM];
__device__ __half g_wlo[4 * WELEM];

// ---------------------------------------------------------------------------
__device__ __forceinline__ void fp16_split(float v, __half& hi, __half& lo)
{
    hi = __float2half_rn(v);
    lo = __float2half_rn(v - __half2float(hi));
}

// W conversion: 4 x 16384 elements (tiny, ~2 us)
__global__ __launch_bounds__(256) void convert_w(const float* __restrict__ wq,
                                                 const float* __restrict__ wk,
                                                 const float* __restrict__ wv,
                                                 const float* __restrict__ wo)
{
    int i = blockIdx.x * blockDim.x + threadIdx.x;
    if (i >= 4 * WELEM) return;
    const float* src[4] = { wq, wk, wv, wo };
    float v = src[i >> 14][i & (WELEM - 1)];
    __half hi, lo;
    fp16_split(v, hi, lo);
    g_whi[i] = hi;
    g_wlo[i] = lo;
}

// ---------------------------------------------------------------------------
// Persistent-W FP16 2-pass tensor GEMM: C[m][n] = sum_k A[m][k]*W[n][k].
// A converted to single fp16 in-kernel (err 2^-12 RMS); W = fp16 hi+lo
// resident in smem -> acc = Ah*Wh + Ah*Wl. One A plane per buffer (LDS
// traffic -17%, MMA -33% vs bf16 3-pass). R8 tiling otherwise: 32-row
// tiles, 8 warps (2m x 4n, warp tile m16 x n32), double-buffered A.
// Row stride 136 elem (272 B): ldmatrix 8-row phases conflict-free.
// ---------------------------------------------------------------------------
#define MMA_F16(d, a, b)                                                    \
    asm volatile(                                                           \
        "mma.sync.aligned.m16n8k16.row.col.f32.f16.f16.f32 "                \
        "{%0,%1,%2,%3}, {%4,%5,%6,%7}, {%8,%9}, {%0,%1,%2,%3};"             \
        : "+f"(d[0]), "+f"(d[1]), "+f"(d[2]), "+f"(d[3])                    \
        : "r"(a[0]), "r"(a[1]), "r"(a[2]), "r"(a[3]), "r"(b[0]), "r"(b[1]))

__device__ __forceinline__ void ldsm4(unsigned* r, unsigned addr)
{
    asm volatile("ldmatrix.sync.aligned.m8n8.x4.shared.b16 {%0,%1,%2,%3}, [%4];"
                 : "=r"(r[0]), "=r"(r[1]), "=r"(r[2]), "=r"(r[3]) : "r"(addr));
}

#define SROWW   136                        // row stride in fp16 elems (272 B)
#define WPLANE  (128 * SROWW)              // 17408 elems
#define ATILE   (32 * SROWW)               // 4352 elems (single A plane)
#define OFF_WL  WPLANE
#define OFF_A   (2 * WPLANE)               // A buffers start
#define GSMEM_ELEM (2 * WPLANE + 2 * ATILE) // 43520 elems
#define GSMEM_BYTES (GSMEM_ELEM * 2)       // 87040 B

__global__ __launch_bounds__(256, 2) void gemm_f16(const float* __restrict__ A,
                                                   const __half* __restrict__ WhiB,
                                                   const __half* __restrict__ WloB,
                                                   const float* __restrict__ bias,
                                                   float* __restrict__ Cf,
                                                   __half* __restrict__ Ck,
                                                   __half* __restrict__ Cv,
                                                   int wsel)
{
    extern __shared__ __half smem[];

    const int y    = blockIdx.y;
    const int widx = wsel + y;
    const __half* Wh = WhiB + widx * WELEM;
    const __half* Wl = WloB + widx * WELEM;

    const int tid  = threadIdx.x;
    const int w    = tid >> 5;
    const int lane = tid & 31;
    const int wm   = (w >> 2) * 16;     // 2 warps in m
    const int wn   = (w & 3) * 32;      // 4 warps in n
    const int fr   = lane >> 2;
    const int fc   = (lane & 3) * 2;

    // ---- load W (hi+lo fp16) into smem, once ----
    #pragma unroll
    for (int it = 0; it < 8; it++) {
        int i   = tid + it * 256;            // 0..2047 (uint4 granules)
        int row = i >> 4;
        int seg = i & 15;
        *(uint4*)&smem[row * SROWW + seg * 8] =
            *(const uint4*)&Wh[row * DDIM + seg * 8];
        *(uint4*)&smem[OFF_WL + row * SROWW + seg * 8] =
            *(const uint4*)&Wl[row * DDIM + seg * 8];
    }

    const unsigned sbase = (unsigned)__cvta_generic_to_shared(&smem[0]);
    const unsigned laneA = (unsigned)((wm + (lane & 15)) * (SROWW * 2)
                                      + ((lane >> 4) & 1) * 16);
    const unsigned laneB = (unsigned)((wn + ((lane >> 4) & 1) * 8 + (lane & 7)) * (SROWW * 2)
                                      + ((lane >> 3) & 1) * 16);
    const unsigned aoff[2] = { (unsigned)(OFF_A * 2), (unsigned)((OFF_A + ATILE) * 2) };

    // A staging: thread owns row ar (8 thr/row), 16 floats at seg as*16
    const int ar = tid >> 3;            // 0..31
    const int as = tid & 7;

    float4 aR[4];
    auto stage = [&](int mt) {
        const float4* s = (const float4*)&A[(size_t)(mt * 32 + ar) * DDIM + as * 16];
        aR[0] = s[0]; aR[1] = s[1]; aR[2] = s[2]; aR[3] = s[3];
    };
    auto commit = [&](int b) {
        __half* ah = &smem[OFF_A + b * ATILE];
        union { __half h[16]; uint4 u[2]; } H;
        const float* af = (const float*)aR;
        #pragma unroll
        for (int i = 0; i < 16; i++) H.h[i] = __float2half_rn(af[i]);
        uint4* dh = (uint4*)&ah[ar * SROWW + as * 16];
        dh[0] = H.u[0]; dh[1] = H.u[1];
    };

    int mt = blockIdx.x;
    int buf = 0;
    if (mt < NTILES) { stage(mt); commit(0); }
    __syncthreads();                     // covers W load + first A commit

    while (mt < NTILES) {
        const int nxt = mt + gridDim.x;
        if (nxt < NTILES) stage(nxt);

        float acc[4][4] = {};
        const unsigned ab = sbase + aoff[buf];

        #pragma unroll
        for (int ks = 0; ks < 8; ks++) {
            unsigned ah[4];
            ldsm4(ah, ab + laneA + (unsigned)(ks * 32));
            #pragma unroll
            for (int ntp = 0; ntp < 2; ntp++) {
                unsigned bh[4], bl[4];
                const unsigned bo = laneB + (unsigned)(ntp * 16 * SROWW * 2 + ks * 32);
                ldsm4(bh, sbase + bo);
                ldsm4(bl, sbase + (unsigned)(OFF_WL * 2) + bo);
                MMA_F16(acc[ntp * 2],     ah, (bh + 0));
                MMA_F16(acc[ntp * 2],     ah, (bl + 0));
                MMA_F16(acc[ntp * 2 + 1], ah, (bh + 2));
                MMA_F16(acc[ntp * 2 + 1], ah, (bl + 2));
            }
        }

        const int mrow = mt * 32 + wm + fr;
        if (y == 0) {
            #pragma unroll
            for (int nt = 0; nt < 4; nt++) {
                const int n = wn + nt * 8 + fc;
                float2 bb = make_float2(0.f, 0.f);
                if (bias) bb = *(const float2*)&bias[n];
                *(float2*)&Cf[(size_t)mrow * DDIM + n] =
                    make_float2(acc[nt][0] + bb.x, acc[nt][1] + bb.y);
                *(float2*)&Cf[(size_t)(mrow + 8) * DDIM + n] =
                    make_float2(acc[nt][2] + bb.x, acc[nt][3] + bb.y);
            }
        } else {
            __half* H = (y == 1) ? Ck : Cv;
            #pragma unroll
            for (int nt = 0; nt < 4; nt++) {
                const int n = wn + nt * 8 + fc;
                *(__half2*)&H[(size_t)mrow * DDIM + n] =
                    __floats2half2_rn(acc[nt][0], acc[nt][1]);
                *(__half2*)&H[(size_t)(mrow + 8) * DDIM + n] =
                    __floats2half2_rn(acc[nt][2], acc[nt][3]);
            }
        }

        if (nxt < NTILES) commit(buf ^ 1);
        __syncthreads();
        buf ^= 1;
        mt = nxt;
    }
}

// ---------------------------------------------------------------------------
// Attention (R14 — best measured): ONE WARP PER QUERY, zero smem/barriers.
// Lane layout: j = lane&15 owns channels [8j, 8j+8); b = lane>>4 = key half.
// Scores in regs; one shfl_xor(1) per key pair; no-max softmax; V in regs.
// ---------------------------------------------------------------------------
__global__ __launch_bounds__(256) void attn_kernel(const int* __restrict__ kidx)
{
    const int W    = threadIdx.x >> 5;
    const int lane = threadIdx.x & 31;
    const int bl   = blockIdx.x * 8 + W;       // query row (b*L + l)
    const int l    = bl % LQ;
    const int base = bl - l;
    const int b    = lane >> 4;                // key half (0/1)
    const int j    = lane & 15;                // channel chunk

    // lane i holds key i's index
    const int myIdx = kidx[l * KSEL + lane];

    // q chunk: channels [8j, 8j+8)
    const float4 qa = *(const float4*)&g_q[(size_t)bl * DDIM + j * 8];
    const float4 qb = *(const float4*)&g_q[(size_t)bl * DDIM + j * 8 + 4];

    // ---- score phase ----
    float s[16];
    #pragma unroll
    for (int i = 0; i < 16; i++) {
        const int key = 2 * i + b;
        const int row = base + __shfl_sync(0xffffffffu, myIdx, key);
        const uint4 kv = *(const uint4*)&g_kh[(size_t)row * DDIM + j * 8];
        const float2 f0 = __half22float2(*(const __half2*)&kv.x);
        const float2 f1 = __half22float2(*(const __half2*)&kv.y);
        const float2 f2 = __half22float2(*(const __half2*)&kv.z);
        const float2 f3 = __half22float2(*(const __half2*)&kv.w);
        float p = f0.x * qa.x + f0.y * qa.y + f1.x * qa.z + f1.y * qa.w
                + f2.x * qb.x + f2.y * qb.y + f3.x * qb.z + f3.y * qb.w;
        p += __shfl_xor_sync(0xffffffffu, p, 1);   // join 8-ch halves of head j>>1
        s[i] = p * 0.25f;                          // scale = 1/sqrt(16)
    }

    // ---- softmax over this head's 32 keys (no max subtraction) ----
    float sum = 0.f;
    #pragma unroll
    for (int i = 0; i < 16; i++) {
        s[i] = __expf(s[i]);
        sum += s[i];
    }
    sum += __shfl_xor_sync(0xffffffffu, sum, 16);  // join key halves
    const float inv = __frcp_rn(sum);

    // ---- V phase: lane accumulates channels [8j, 8j+8) over its 16 keys ----
    float acc[8] = {};
    #pragma unroll
    for (int i = 0; i < 16; i++) {
        const int key = 2 * i + b;
        const int row = base + __shfl_sync(0xffffffffu, myIdx, key);
        const uint4 vv = *(const uint4*)&g_vh[(size_t)row * DDIM + j * 8];
        const float2 f0 = __half22float2(*(const __half2*)&vv.x);
        const float2 f1 = __half22float2(*(const __half2*)&vv.y);
        const float2 f2 = __half22float2(*(const __half2*)&vv.z);
        const float2 f3 = __half22float2(*(const __half2*)&vv.w);
        const float a = s[i] * inv;
        acc[0] += a * f0.x; acc[1] += a * f0.y;
        acc[2] += a * f1.x; acc[3] += a * f1.y;
        acc[4] += a * f2.x; acc[5] += a * f2.y;
        acc[6] += a * f3.x; acc[7] += a * f3.y;
    }

    // ---- join key halves, store ----
    #pragma unroll
    for (int c = 0; c < 8; c++)
        acc[c] += __shfl_xor_sync(0xffffffffu, acc[c], 16);

    if (b == 0) {
        *(float4*)&g_attn[(size_t)bl * DDIM + j * 8] =
            make_float4(acc[0], acc[1], acc[2], acc[3]);
        *(float4*)&g_attn[(size_t)bl * DDIM + j * 8 + 4] =
            make_float4(acc[4], acc[5], acc[6], acc[7]);
    }
}

// ---------------------------------------------------------------------------
extern "C" void kernel_launch(void* const* d_in, const int* in_sizes, int n_in,
                              void* d_out, int out_size)
{
    const float* x    = (const float*)d_in[0];
    const int*   kidx = (const int*)d_in[1];
    const float* Wq   = (const float*)d_in[2];
    const float* Wk   = (const float*)d_in[3];
    const float* Wv   = (const float*)d_in[4];
    const float* Wo   = (const float*)d_in[5];
    const float* bo   = (const float*)d_in[6];
    float* out = (float*)d_out;

    float *q, *attn;
    __half *kh, *vh, *whi, *wlo;
    cudaGetSymbolAddress((void**)&q,    g_q);
    cudaGetSymbolAddress((void**)&kh,   g_kh);
    cudaGetSymbolAddress((void**)&vh,   g_vh);
    cudaGetSymbolAddress((void**)&attn, g_attn);
    cudaGetSymbolAddress((void**)&whi,  g_whi);
    cudaGetSymbolAddress((void**)&wlo,  g_wlo);

    // Raise dynamic smem cap (idempotent; not a stream op; every call).
    cudaFuncSetAttribute(gemm_f16,
                         cudaFuncAttributeMaxDynamicSharedMemorySize,
                         GSMEM_BYTES);

    convert_w<<<(4 * WELEM + 255) / 256, 256>>>(Wq, Wk, Wv, Wo);

    // QKV: 96 x 3 persistent blocks (~2/SM), ~6.5 tiles each.
    gemm_f16<<<dim3(96, 3), 256, GSMEM_BYTES>>>(x, whi, wlo, nullptr,
                                                q, kh, vh, 0);

    // Attention: 1 warp per query, 8 queries/block, 2500 blocks.
    attn_kernel<<<MROWS / 8, 256>>>(kidx);

    // Wo: 296 persistent blocks (2/SM), ~2.1 tiles each, bias, fp32 out.
    gemm_f16<<<dim3(296, 1), 256, GSMEM_BYTES>>>(attn, whi, wlo, bo,
                                                 out, nullptr, nullptr, 3);
}

// round 16
// speedup vs baseline: 1.3226x; 1.0060x over previous
#include <cuda_runtime.h>
#include <cuda_bf16.h>
#include <cuda_fp16.h>
#include <math.h>

// Problem constants: B=4, L=5000, D=128, H=8, d=16, K=32
#define LQ    5000
#define MROWS 20000          // B*L  (divisible by 32)
#define DDIM  128
#define KSEL  32
#define WELEM (DDIM*DDIM)    // 16384
#define NTILES (MROWS/32)    // 625 tiles of 32 rows

// Scratch (allocation-free rule: __device__ globals)
__device__ float  g_q[MROWS * DDIM];
__device__ __half g_kh[MROWS * DDIM];
__device__ __half g_vh[MROWS * DDIM];
__device__ __half g_attnh[MROWS * DDIM];
__device__ __half g_whi[4 * WELEM];
__device__ __half g_wlo[4 * WELEM];

// ---------------------------------------------------------------------------
__device__ __forceinline__ void fp16_split(float v, __half& hi, __half& lo)
{
    hi = __float2half_rn(v);
    lo = __float2half_rn(v - __half2float(hi));
}

// W conversion: 4 x 16384 elements (tiny, ~2 us)
__global__ __launch_bounds__(256) void convert_w(const float* __restrict__ wq,
                                                 const float* __restrict__ wk,
                                                 const float* __restrict__ wv,
                                                 const float* __restrict__ wo)
{
    int i = blockIdx.x * blockDim.x + threadIdx.x;
    if (i >= 4 * WELEM) return;
    const float* src[4] = { wq, wk, wv, wo };
    float v = src[i >> 14][i & (WELEM - 1)];
    __half hi, lo;
    fp16_split(v, hi, lo);
    g_whi[i] = hi;
    g_wlo[i] = lo;
}

// ---------------------------------------------------------------------------
// Persistent-W FP16 2-pass tensor GEMM, templated on A element type:
//   AT=float : A converted to fp16 at commit (QKV pass)
//   AT=half  : A copied straight through (Wo pass; attn already fp16)
// acc = Ah*Wh + Ah*Wl with W = fp16 hi+lo resident in smem.
// R8 tiling: 32-row tiles, 8 warps (2m x 4n, warp tile m16 x n32),
// double-buffered A. Row stride 136 elem (272 B): ldmatrix conflict-free.
// ---------------------------------------------------------------------------
#define MMA_F16(d, a, b)                                                    \
    asm volatile(                                                           \
        "mma.sync.aligned.m16n8k16.row.col.f32.f16.f16.f32 "                \
        "{%0,%1,%2,%3}, {%4,%5,%6,%7}, {%8,%9}, {%0,%1,%2,%3};"             \
        : "+f"(d[0]), "+f"(d[1]), "+f"(d[2]), "+f"(d[3])                    \
        : "r"(a[0]), "r"(a[1]), "r"(a[2]), "r"(a[3]), "r"(b[0]), "r"(b[1]))

__device__ __forceinline__ void ldsm4(unsigned* r, unsigned addr)
{
    asm volatile("ldmatrix.sync.aligned.m8n8.x4.shared.b16 {%0,%1,%2,%3}, [%4];"
                 : "=r"(r[0]), "=r"(r[1]), "=r"(r[2]), "=r"(r[3]) : "r"(addr));
}

#define SROWW   136                        // row stride in fp16 elems (272 B)
#define WPLANE  (128 * SROWW)              // 17408 elems
#define ATILE   (32 * SROWW)               // 4352 elems (single A plane)
#define OFF_WL  WPLANE
#define OFF_A   (2 * WPLANE)               // A buffers start
#define GSMEM_ELEM (2 * WPLANE + 2 * ATILE) // 43520 elems
#define GSMEM_BYTES (GSMEM_ELEM * 2)       // 87040 B

template <typename AT>
__global__ __launch_bounds__(256, 2) void gemm_f16(const AT* __restrict__ A,
                                                   const __half* __restrict__ WhiB,
                                                   const __half* __restrict__ WloB,
                                                   const float* __restrict__ bias,
                                                   float* __restrict__ Cf,
                                                   __half* __restrict__ Ck,
                                                   __half* __restrict__ Cv,
                                                   int wsel)
{
    extern __shared__ __half smem[];

    const int y    = blockIdx.y;
    const int widx = wsel + y;
    const __half* Wh = WhiB + widx * WELEM;
    const __half* Wl = WloB + widx * WELEM;

    const int tid  = threadIdx.x;
    const int w    = tid >> 5;
    const int lane = tid & 31;
    const int wm   = (w >> 2) * 16;     // 2 warps in m
    const int wn   = (w & 3) * 32;      // 4 warps in n
    const int fr   = lane >> 2;
    const int fc   = (lane & 3) * 2;

    // ---- load W (hi+lo fp16) into smem, once ----
    #pragma unroll
    for (int it = 0; it < 8; it++) {
        int i   = tid + it * 256;            // 0..2047 (uint4 granules)
        int row = i >> 4;
        int seg = i & 15;
        *(uint4*)&smem[row * SROWW + seg * 8] =
            *(const uint4*)&Wh[row * DDIM + seg * 8];
        *(uint4*)&smem[OFF_WL + row * SROWW + seg * 8] =
            *(const uint4*)&Wl[row * DDIM + seg * 8];
    }

    const unsigned sbase = (unsigned)__cvta_generic_to_shared(&smem[0]);
    const unsigned laneA = (unsigned)((wm + (lane & 15)) * (SROWW * 2)
                                      + ((lane >> 4) & 1) * 16);
    const unsigned laneB = (unsigned)((wn + ((lane >> 4) & 1) * 8 + (lane & 7)) * (SROWW * 2)
                                      + ((lane >> 3) & 1) * 16);
    const unsigned aoff[2] = { (unsigned)(OFF_A * 2), (unsigned)((OFF_A + ATILE) * 2) };

    // A staging: thread owns row ar (8 thr/row), 16 elements at seg as*16
    const int ar = tid >> 3;            // 0..31
    const int as = tid & 7;

    float4 aR[4];     // used when AT = float
    uint4  hR[2];     // used when AT = __half

    auto stage = [&](int mt) {
        if constexpr (sizeof(AT) == 4) {
            const float4* s = (const float4*)&A[(size_t)(mt * 32 + ar) * DDIM + as * 16];
            aR[0] = s[0]; aR[1] = s[1]; aR[2] = s[2]; aR[3] = s[3];
        } else {
            const uint4* s = (const uint4*)&A[(size_t)(mt * 32 + ar) * DDIM + as * 16];
            hR[0] = s[0]; hR[1] = s[1];
        }
    };
    auto commit = [&](int b) {
        __half* ah = &smem[OFF_A + b * ATILE];
        uint4* dh = (uint4*)&ah[ar * SROWW + as * 16];
        if constexpr (sizeof(AT) == 4) {
            union { __half h[16]; uint4 u[2]; } H;
            const float* af = (const float*)aR;
            #pragma unroll
            for (int i = 0; i < 16; i++) H.h[i] = __float2half_rn(af[i]);
            dh[0] = H.u[0]; dh[1] = H.u[1];
        } else {
            dh[0] = hR[0]; dh[1] = hR[1];
        }
    };

    int mt = blockIdx.x;
    int buf = 0;
    if (mt < NTILES) { stage(mt); commit(0); }
    __syncthreads();                     // covers W load + first A commit

    while (mt < NTILES) {
        const int nxt = mt + gridDim.x;
        if (nxt < NTILES) stage(nxt);

        float acc[4][4] = {};
        const unsigned ab = sbase + aoff[buf];

        #pragma unroll
        for (int ks = 0; ks < 8; ks++) {
            unsigned ah[4];
            ldsm4(ah, ab + laneA + (unsigned)(ks * 32));
            #pragma unroll
            for (int ntp = 0; ntp < 2; ntp++) {
                unsigned bh[4], bl[4];
                const unsigned bo = laneB + (unsigned)(ntp * 16 * SROWW * 2 + ks * 32);
                ldsm4(bh, sbase + bo);
                ldsm4(bl, sbase + (unsigned)(OFF_WL * 2) + bo);
                MMA_F16(acc[ntp * 2],     ah, (bh + 0));
                MMA_F16(acc[ntp * 2],     ah, (bl + 0));
                MMA_F16(acc[ntp * 2 + 1], ah, (bh + 2));
                MMA_F16(acc[ntp * 2 + 1], ah, (bl + 2));
            }
        }

        const int mrow = mt * 32 + wm + fr;
        if (y == 0 && Cf) {
            #pragma unroll
            for (int nt = 0; nt < 4; nt++) {
                const int n = wn + nt * 8 + fc;
                float2 bb = make_float2(0.f, 0.f);
                if (bias) bb = *(const float2*)&bias[n];
                *(float2*)&Cf[(size_t)mrow * DDIM + n] =
                    make_float2(acc[nt][0] + bb.x, acc[nt][1] + bb.y);
                *(float2*)&Cf[(size_t)(mrow + 8) * DDIM + n] =
                    make_float2(acc[nt][2] + bb.x, acc[nt][3] + bb.y);
            }
        } else {
            __half* H = (y == 1) ? Ck : Cv;
            #pragma unroll
            for (int nt = 0; nt < 4; nt++) {
                const int n = wn + nt * 8 + fc;
                *(__half2*)&H[(size_t)mrow * DDIM + n] =
                    __floats2half2_rn(acc[nt][0], acc[nt][1]);
                *(__half2*)&H[(size_t)(mrow + 8) * DDIM + n] =
                    __floats2half2_rn(acc[nt][2], acc[nt][3]);
            }
        }

        if (nxt < NTILES) commit(buf ^ 1);
        __syncthreads();
        buf ^= 1;
        mt = nxt;
    }
}

// ---------------------------------------------------------------------------
// Attention (R14 structure): ONE WARP PER QUERY, zero smem/barriers.
// Lane layout: j = lane&15 owns channels [8j, 8j+8); b = lane>>4 = key half.
// Scores in regs; one shfl_xor(1) per key pair; no-max softmax; V in regs.
// Output now fp16 (one STG.128 per lane b==0).
// ---------------------------------------------------------------------------
__global__ __launch_bounds__(256) void attn_kernel(const int* __restrict__ kidx)
{
    const int W    = threadIdx.x >> 5;
    const int lane = threadIdx.x & 31;
    const int bl   = blockIdx.x * 8 + W;       // query row (b*L + l)
    const int l    = bl % LQ;
    const int base = bl - l;
    const int b    = lane >> 4;                // key half (0/1)
    const int j    = lane & 15;                // channel chunk

    // lane i holds key i's index
    const int myIdx = kidx[l * KSEL + lane];

    // q chunk: channels [8j, 8j+8)
    const float4 qa = *(const float4*)&g_q[(size_t)bl * DDIM + j * 8];
    const float4 qb = *(const float4*)&g_q[(size_t)bl * DDIM + j * 8 + 4];

    // ---- score phase ----
    float s[16];
    #pragma unroll
    for (int i = 0; i < 16; i++) {
        const int key = 2 * i + b;
        const int row = base + __shfl_sync(0xffffffffu, myIdx, key);
        const uint4 kv = *(const uint4*)&g_kh[(size_t)row * DDIM + j * 8];
        const float2 f0 = __half22float2(*(const __half2*)&kv.x);
        const float2 f1 = __half22float2(*(const __half2*)&kv.y);
        const float2 f2 = __half22float2(*(const __half2*)&kv.z);
        const float2 f3 = __half22float2(*(const __half2*)&kv.w);
        float p = f0.x * qa.x + f0.y * qa.y + f1.x * qa.z + f1.y * qa.w
                + f2.x * qb.x + f2.y * qb.y + f3.x * qb.z + f3.y * qb.w;
        p += __shfl_xor_sync(0xffffffffu, p, 1);   // join 8-ch halves of head j>>1
        s[i] = p * 0.25f;                          // scale = 1/sqrt(16)
    }

    // ---- softmax over this head's 32 keys (no max subtraction) ----
    float sum = 0.f;
    #pragma unroll
    for (int i = 0; i < 16; i++) {
        s[i] = __expf(s[i]);
        sum += s[i];
    }
    sum += __shfl_xor_sync(0xffffffffu, sum, 16);  // join key halves
    const float inv = __frcp_rn(sum);

    // ---- V phase: lane accumulates channels [8j, 8j+8) over its 16 keys ----
    float acc[8] = {};
    #pragma unroll
    for (int i = 0; i < 16; i++) {
        const int key = 2 * i + b;
        const int row = base + __shfl_sync(0xffffffffu, myIdx, key);
        const uint4 vv = *(const uint4*)&g_vh[(size_t)row * DDIM + j * 8];
        const float2 f0 = __half22float2(*(const __half2*)&vv.x);
        const float2 f1 = __half22float2(*(const __half2*)&vv.y);
        const float2 f2 = __half22float2(*(const __half2*)&vv.z);
        const float2 f3 = __half22float2(*(const __half2*)&vv.w);
        const float a = s[i] * inv;
        acc[0] += a * f0.x; acc[1] += a * f0.y;
        acc[2] += a * f1.x; acc[3] += a * f1.y;
        acc[4] += a * f2.x; acc[5] += a * f2.y;
        acc[6] += a * f3.x; acc[7] += a * f3.y;
    }

    // ---- join key halves, store fp16 (one STG.128) ----
    #pragma unroll
    for (int c = 0; c < 8; c++)
        acc[c] += __shfl_xor_sync(0xffffffffu, acc[c], 16);

    if (b == 0) {
        union { __half2 h2[4]; uint4 u; } O;
        O.h2[0] = __floats2half2_rn(acc[0], acc[1]);
        O.h2[1] = __floats2half2_rn(acc[2], acc[3]);
        O.h2[2] = __floats2half2_rn(acc[4], acc[5]);
        O.h2[3] = __floats2half2_rn(acc[6], acc[7]);
        *(uint4*)&g_attnh[(size_t)bl * DDIM + j * 8] = O.u;
    }
}

// ---------------------------------------------------------------------------
extern "C" void kernel_launch(void* const* d_in, const int* in_sizes, int n_in,
                              void* d_out, int out_size)
{
    const float* x    = (const float*)d_in[0];
    const int*   kidx = (const int*)d_in[1];
    const float* Wq   = (const float*)d_in[2];
    const float* Wk   = (const float*)d_in[3];
    const float* Wv   = (const float*)d_in[4];
    const float* Wo   = (const float*)d_in[5];
    const float* bo   = (const float*)d_in[6];
    float* out = (float*)d_out;

    float *q;
    __half *kh, *vh, *attnh, *whi, *wlo;
    cudaGetSymbolAddress((void**)&q,     g_q);
    cudaGetSymbolAddress((void**)&kh,    g_kh);
    cudaGetSymbolAddress((void**)&vh,    g_vh);
    cudaGetSymbolAddress((void**)&attnh, g_attnh);
    cudaGetSymbolAddress((void**)&whi,   g_whi);
    cudaGetSymbolAddress((void**)&wlo,   g_wlo);

    // Raise dynamic smem cap on both instantiations (idempotent; every call).
    cudaFuncSetAttribute(gemm_f16<float>,
                         cudaFuncAttributeMaxDynamicSharedMemorySize,
                         GSMEM_BYTES);
    cudaFuncSetAttribute(gemm_f16<__half>,
                         cudaFuncAttributeMaxDynamicSharedMemorySize,
                         GSMEM_BYTES);

    convert_w<<<(4 * WELEM + 255) / 256, 256>>>(Wq, Wk, Wv, Wo);

    // QKV: 96 x 3 persistent blocks (~2/SM), ~6.5 tiles each. A = fp32 x.
    gemm_f16<float><<<dim3(96, 3), 256, GSMEM_BYTES>>>(x, whi, wlo, nullptr,
                                                       q, kh, vh, 0);

    // Attention: 1 warp per query, 8 queries/block, 2500 blocks. fp16 out.
    attn_kernel<<<MROWS / 8, 256>>>(kidx);

    // Wo: 296 persistent blocks (2/SM), ~2.1 tiles each. A = fp16 attn.
    gemm_f16<__half><<<dim3(296, 1), 256, GSMEM_BYTES>>>(attnh, whi, wlo, bo,
                                                         out, nullptr, nullptr, 3);
}

// round 17
// speedup vs baseline: 1.4635x; 1.1065x over previous
#include <cuda_runtime.h>
#include <cuda_bf16.h>
#include <cuda_fp16.h>
#include <math.h>

// Problem constants: B=4, L=5000, D=128, H=8, d=16, K=32
#define LQ    5000
#define MROWS 20000          // B*L  (divisible by 32)
#define DDIM  128
#define KSEL  32
#define WELEM (DDIM*DDIM)    // 16384
#define NTILES (MROWS/32)    // 625 tiles of 32 rows

// Scratch (allocation-free rule: __device__ globals)
__device__ float  g_q[MROWS * DDIM];
__device__ __half g_kh[MROWS * DDIM];
__device__ __half g_vh[MROWS * DDIM];
__device__ __half g_attnh[MROWS * DDIM];
__device__ __half g_wh[4 * WELEM];

// ---------------------------------------------------------------------------
// W conversion: 4 x 16384 elements -> single fp16 (tiny, ~1.5 us)
__global__ __launch_bounds__(256) void convert_w(const float* __restrict__ wq,
                                                 const float* __restrict__ wk,
                                                 const float* __restrict__ wv,
                                                 const float* __restrict__ wo)
{
    int i = blockIdx.x * blockDim.x + threadIdx.x;
    if (i >= 4 * WELEM) return;
    const float* src[4] = { wq, wk, wv, wo };
    g_wh[i] = __float2half_rn(src[i >> 14][i & (WELEM - 1)]);
}

// ---------------------------------------------------------------------------
// Persistent-W single-pass FP16 tensor GEMM, templated on A element type:
//   AT=float : A converted to fp16 at commit (QKV pass)
//   AT=half  : A copied straight through (Wo pass; attn already fp16)
// W = single fp16 plane resident in smem (34 KB). Block footprint 52 KB ->
// 4 blocks/SM (occ ~48%). R8 tiling: 32-row tiles, 8 warps (2m x 4n,
// warp tile m16 x n32), double-buffered A. Row stride 136 elem (272 B):
// ldmatrix 8-row phases conflict-free.
// ---------------------------------------------------------------------------
#define MMA_F16(d, a, b)                                                    \
    asm volatile(                                                           \
        "mma.sync.aligned.m16n8k16.row.col.f32.f16.f16.f32 "                \
        "{%0,%1,%2,%3}, {%4,%5,%6,%7}, {%8,%9}, {%0,%1,%2,%3};"             \
        : "+f"(d[0]), "+f"(d[1]), "+f"(d[2]), "+f"(d[3])                    \
        : "r"(a[0]), "r"(a[1]), "r"(a[2]), "r"(a[3]), "r"(b[0]), "r"(b[1]))

__device__ __forceinline__ void ldsm4(unsigned* r, unsigned addr)
{
    asm volatile("ldmatrix.sync.aligned.m8n8.x4.shared.b16 {%0,%1,%2,%3}, [%4];"
                 : "=r"(r[0]), "=r"(r[1]), "=r"(r[2]), "=r"(r[3]) : "r"(addr));
}

#define SROWW   136                        // row stride in fp16 elems (272 B)
#define WPLANE  (128 * SROWW)              // 17408 elems (34816 B)
#define ATILE   (32 * SROWW)               // 4352 elems (single A plane)
#define OFF_A   WPLANE                     // A buffers start
#define GSMEM_ELEM (WPLANE + 2 * ATILE)    // 26112 elems
#define GSMEM_BYTES (GSMEM_ELEM * 2)       // 52224 B

template <typename AT>
__global__ __launch_bounds__(256, 4) void gemm_f16(const AT* __restrict__ A,
                                                   const __half* __restrict__ WB,
                                                   const float* __restrict__ bias,
                                                   float* __restrict__ Cf,
                                                   __half* __restrict__ Ck,
                                                   __half* __restrict__ Cv,
                                                   int wsel)
{
    extern __shared__ __half smem[];

    const int y    = blockIdx.y;
    const __half* Wm = WB + (wsel + y) * WELEM;

    const int tid  = threadIdx.x;
    const int w    = tid >> 5;
    const int lane = tid & 31;
    const int wm   = (w >> 2) * 16;     // 2 warps in m
    const int wn   = (w & 3) * 32;      // 4 warps in n
    const int fr   = lane >> 2;
    const int fc   = (lane & 3) * 2;

    // ---- load W (fp16) into smem, once ----
    #pragma unroll
    for (int it = 0; it < 8; it++) {
        int i   = tid + it * 256;            // 0..2047 (uint4 granules)
        int row = i >> 4;
        int seg = i & 15;
        *(uint4*)&smem[row * SROWW + seg * 8] =
            *(const uint4*)&Wm[row * DDIM + seg * 8];
    }

    const unsigned sbase = (unsigned)__cvta_generic_to_shared(&smem[0]);
    const unsigned laneA = (unsigned)((wm + (lane & 15)) * (SROWW * 2)
                                      + ((lane >> 4) & 1) * 16);
    const unsigned laneB = (unsigned)((wn + ((lane >> 4) & 1) * 8 + (lane & 7)) * (SROWW * 2)
                                      + ((lane >> 3) & 1) * 16);
    const unsigned aoff[2] = { (unsigned)(OFF_A * 2), (unsigned)((OFF_A + ATILE) * 2) };

    // A staging: thread owns row ar (8 thr/row), 16 elements at seg as*16
    const int ar = tid >> 3;            // 0..31
    const int as = tid & 7;

    float4 aR[4];     // used when AT = float
    uint4  hR[2];     // used when AT = __half

    auto stage = [&](int mt) {
        if constexpr (sizeof(AT) == 4) {
            const float4* s = (const float4*)&A[(size_t)(mt * 32 + ar) * DDIM + as * 16];
            aR[0] = s[0]; aR[1] = s[1]; aR[2] = s[2]; aR[3] = s[3];
        } else {
            const uint4* s = (const uint4*)&A[(size_t)(mt * 32 + ar) * DDIM + as * 16];
            hR[0] = s[0]; hR[1] = s[1];
        }
    };
    auto commit = [&](int b) {
        __half* ah = &smem[OFF_A + b * ATILE];
        uint4* dh = (uint4*)&ah[ar * SROWW + as * 16];
        if constexpr (sizeof(AT) == 4) {
            union { __half h[16]; uint4 u[2]; } H;
            const float* af = (const float*)aR;
            #pragma unroll
            for (int i = 0; i < 16; i++) H.h[i] = __float2half_rn(af[i]);
            dh[0] = H.u[0]; dh[1] = H.u[1];
        } else {
            dh[0] = hR[0]; dh[1] = hR[1];
        }
    };

    int mt = blockIdx.x;
    int buf = 0;
    if (mt < NTILES) { stage(mt); commit(0); }
    __syncthreads();                     // covers W load + first A commit

    while (mt < NTILES) {
        const int nxt = mt + gridDim.x;
        if (nxt < NTILES) stage(nxt);

        float acc[4][4] = {};
        const unsigned ab = sbase + aoff[buf];

        #pragma unroll
        for (int ks = 0; ks < 8; ks++) {
            unsigned ah[4];
            ldsm4(ah, ab + laneA + (unsigned)(ks * 32));
            #pragma unroll
            for (int ntp = 0; ntp < 2; ntp++) {
                unsigned bh[4];
                ldsm4(bh, sbase + laneB + (unsigned)(ntp * 16 * SROWW * 2 + ks * 32));
                MMA_F16(acc[ntp * 2],     ah, (bh + 0));
                MMA_F16(acc[ntp * 2 + 1], ah, (bh + 2));
            }
        }

        const int mrow = mt * 32 + wm + fr;
        if (y == 0 && Cf) {
            #pragma unroll
            for (int nt = 0; nt < 4; nt++) {
                const int n = wn + nt * 8 + fc;
                float2 bb = make_float2(0.f, 0.f);
                if (bias) bb = *(const float2*)&bias[n];
                *(float2*)&Cf[(size_t)mrow * DDIM + n] =
                    make_float2(acc[nt][0] + bb.x, acc[nt][1] + bb.y);
                *(float2*)&Cf[(size_t)(mrow + 8) * DDIM + n] =
                    make_float2(acc[nt][2] + bb.x, acc[nt][3] + bb.y);
            }
        } else {
            __half* H = (y == 1) ? Ck : Cv;
            #pragma unroll
            for (int nt = 0; nt < 4; nt++) {
                const int n = wn + nt * 8 + fc;
                *(__half2*)&H[(size_t)mrow * DDIM + n] =
                    __floats2half2_rn(acc[nt][0], acc[nt][1]);
                *(__half2*)&H[(size_t)(mrow + 8) * DDIM + n] =
                    __floats2half2_rn(acc[nt][2], acc[nt][3]);
            }
        }

        if (nxt < NTILES) commit(buf ^ 1);
        __syncthreads();
        buf ^= 1;
        mt = nxt;
    }
}

// ---------------------------------------------------------------------------
// Attention (R14/R16 — best measured): ONE WARP PER QUERY, zero smem/barriers.
// Lane layout: j = lane&15 owns channels [8j, 8j+8); b = lane>>4 = key half.
// Scores in regs; one shfl_xor(1) per key pair; no-max softmax; V in regs;
// fp16 output (one STG.128 per lane b==0).
// ---------------------------------------------------------------------------
__global__ __launch_bounds__(256) void attn_kernel(const int* __restrict__ kidx)
{
    const int W    = threadIdx.x >> 5;
    const int lane = threadIdx.x & 31;
    const int bl   = blockIdx.x * 8 + W;       // query row (b*L + l)
    const int l    = bl % LQ;
    const int base = bl - l;
    const int b    = lane >> 4;                // key half (0/1)
    const int j    = lane & 15;                // channel chunk

    // lane i holds key i's index
    const int myIdx = kidx[l * KSEL + lane];

    // q chunk: channels [8j, 8j+8)
    const float4 qa = *(const float4*)&g_q[(size_t)bl * DDIM + j * 8];
    const float4 qb = *(const float4*)&g_q[(size_t)bl * DDIM + j * 8 + 4];

    // ---- score phase ----
    float s[16];
    #pragma unroll
    for (int i = 0; i < 16; i++) {
        const int key = 2 * i + b;
        const int row = base + __shfl_sync(0xffffffffu, myIdx, key);
        const uint4 kv = *(const uint4*)&g_kh[(size_t)row * DDIM + j * 8];
        const float2 f0 = __half22float2(*(const __half2*)&kv.x);
        const float2 f1 = __half22float2(*(const __half2*)&kv.y);
        const float2 f2 = __half22float2(*(const __half2*)&kv.z);
        const float2 f3 = __half22float2(*(const __half2*)&kv.w);
        float p = f0.x * qa.x + f0.y * qa.y + f1.x * qa.z + f1.y * qa.w
                + f2.x * qb.x + f2.y * qb.y + f3.x * qb.z + f3.y * qb.w;
        p += __shfl_xor_sync(0xffffffffu, p, 1);   // join 8-ch halves of head j>>1
        s[i] = p * 0.25f;                          // scale = 1/sqrt(16)
    }

    // ---- softmax over this head's 32 keys (no max subtraction) ----
    float sum = 0.f;
    #pragma unroll
    for (int i = 0; i < 16; i++) {
        s[i] = __expf(s[i]);
        sum += s[i];
    }
    sum += __shfl_xor_sync(0xffffffffu, sum, 16);  // join key halves
    const float inv = __frcp_rn(sum);

    // ---- V phase: lane accumulates channels [8j, 8j+8) over its 16 keys ----
    float acc[8] = {};
    #pragma unroll
    for (int i = 0; i < 16; i++) {
        const int key = 2 * i + b;
        const int row = base + __shfl_sync(0xffffffffu, myIdx, key);
        const uint4 vv = *(const uint4*)&g_vh[(size_t)row * DDIM + j * 8];
        const float2 f0 = __half22float2(*(const __half2*)&vv.x);
        const float2 f1 = __half22float2(*(const __half2*)&vv.y);
        const float2 f2 = __half22float2(*(const __half2*)&vv.z);
        const float2 f3 = __half22float2(*(const __half2*)&vv.w);
        const float a = s[i] * inv;
        acc[0] += a * f0.x; acc[1] += a * f0.y;
        acc[2] += a * f1.x; acc[3] += a * f1.y;
        acc[4] += a * f2.x; acc[5] += a * f2.y;
        acc[6] += a * f3.x; acc[7] += a * f3.y;
    }

    // ---- join key halves, store fp16 (one STG.128) ----
    #pragma unroll
    for (int c = 0; c < 8; c++)
        acc[c] += __shfl_xor_sync(0xffffffffu, acc[c], 16);

    if (b == 0) {
        union { __half2 h2[4]; uint4 u; } O;
        O.h2[0] = __floats2half2_rn(acc[0], acc[1]);
        O.h2[1] = __floats2half2_rn(acc[2], acc[3]);
        O.h2[2] = __floats2half2_rn(acc[4], acc[5]);
        O.h2[3] = __floats2half2_rn(acc[6], acc[7]);
        *(uint4*)&g_attnh[(size_t)bl * DDIM + j * 8] = O.u;
    }
}

// ---------------------------------------------------------------------------
extern "C" void kernel_launch(void* const* d_in, const int* in_sizes, int n_in,
                              void* d_out, int out_size)
{
    const float* x    = (const float*)d_in[0];
    const int*   kidx = (const int*)d_in[1];
    const float* Wq   = (const float*)d_in[2];
    const float* Wk   = (const float*)d_in[3];
    const float* Wv   = (const float*)d_in[4];
    const float* Wo   = (const float*)d_in[5];
    const float* bo   = (const float*)d_in[6];
    float* out = (float*)d_out;

    float *q;
    __half *kh, *vh, *attnh, *wh;
    cudaGetSymbolAddress((void**)&q,     g_q);
    cudaGetSymbolAddress((void**)&kh,    g_kh);
    cudaGetSymbolAddress((void**)&vh,    g_vh);
    cudaGetSymbolAddress((void**)&attnh, g_attnh);
    cudaGetSymbolAddress((void**)&wh,    g_wh);

    // Raise dynamic smem cap on both instantiations (idempotent; every call).
    cudaFuncSetAttribute(gemm_f16<float>,
                         cudaFuncAttributeMaxDynamicSharedMemorySize,
                         GSMEM_BYTES);
    cudaFuncSetAttribute(gemm_f16<__half>,
                         cudaFuncAttributeMaxDynamicSharedMemorySize,
                         GSMEM_BYTES);

    convert_w<<<(4 * WELEM + 255) / 256, 256>>>(Wq, Wk, Wv, Wo);

    // QKV: 96 x 3 persistent blocks (~2/SM at 4-deep occupancy headroom).
    gemm_f16<float><<<dim3(96, 3), 256, GSMEM_BYTES>>>(x, wh, nullptr,
                                                       q, kh, vh, 0);

    // Attention: 1 warp per query, 8 queries/block, 2500 blocks. fp16 out.
    attn_kernel<<<MROWS / 8, 256>>>(kidx);

    // Wo: 592 persistent blocks (4/SM), ~1.05 tiles each. A = fp16 attn.
    gemm_f16<__half><<<dim3(592, 1), 256, GSMEM_BYTES>>>(attnh, wh, bo,
                                                         out, nullptr, nullptr, 3);
}